// round 1
// baseline (speedup 1.0000x reference)
#include <cuda_runtime.h>

// Problem constants
#define Bq 8
#define Sq 2048
#define Hq 1024
#define Mq (Bq*Sq)   // 16384

// ---------------- scratch (device globals; no cudaMalloc allowed) ----------
__device__ float g_Qb[(size_t)Mq*Hq];        // 64 MB
__device__ float g_Kb[(size_t)Mq*Hq];        // 64 MB
__device__ float g_Vb[(size_t)Mq*Hq];        // 64 MB
__device__ float g_Pb[(size_t)Bq*Sq*Sq];     // 134 MB (softmax probs)
__device__ float g_ctxq[Bq*Hq];
__device__ float g_ctxk[Bq*Hq];
__device__ float g_cq[Bq];
__device__ float g_ck[Bq];

// ---------------- packed f32x2 helpers ----------------
__device__ __forceinline__ void fma2(unsigned long long& d,
                                     unsigned long long a,
                                     unsigned long long b) {
    asm("fma.rn.f32x2 %0, %1, %2, %0;" : "+l"(d) : "l"(a), "l"(b));
}
__device__ __forceinline__ float2 unpack2(unsigned long long v) {
    unsigned int lo, hi;
    asm("mov.b64 {%0, %1}, %2;" : "=r"(lo), "=r"(hi) : "l"(v));
    return make_float2(__uint_as_float(lo), __uint_as_float(hi));
}

// ---------------- SGEMM: C = A * op(B) * scale (+bias) ----------------
// A: [M,K] row-major. BT=true: B is [N,K] row-major (C=A*B^T, "NT").
//                     BT=false: B is [K,N] row-major ("NN").
// 128x128 tile, BK=16, 256 threads, 8x8 per thread, FFMA2 inner loop.
#define BMt 128
#define BNt 128
#define BKt 16

template<bool BT, bool HASBIAS>
__global__ void __launch_bounds__(256, 2)
sgemm_k(const float* __restrict__ Ag, const float* __restrict__ Bg,
        float* __restrict__ Cg, const float* __restrict__ bias,
        int M, int N, int K,
        long long sA, long long sB, long long sC, float scale)
{
    __shared__ float AsD[BKt][2*BMt + 4];   // A values duplicated (pairs) for f32x2
    __shared__ float Bs[BKt][BNt + 4];

    const float* A  = Ag + (long long)blockIdx.z * sA;
    const float* Bp = Bg + (long long)blockIdx.z * sB;
    float*       C  = Cg + (long long)blockIdx.z * sC;

    const int bm = blockIdx.y * BMt;
    const int bn = blockIdx.x * BNt;
    const int tid = threadIdx.x;
    const int tx = tid & 15;       // 0..15 -> 8 cols each
    const int ty = tid >> 4;       // 0..15 -> 8 rows each

    // A/B(NT) loader indices: 128 rows x 4 float4-cols
    const int arow0 = tid >> 2;    // 0..63
    const int ac4   = tid & 3;     // 0..3
    // B(NN) loader indices: 16 rows x 32 float4-cols
    const int br  = tid >> 5;      // 0..7
    const int bc4 = tid & 31;      // 0..31

    unsigned long long acc[8][4];
    #pragma unroll
    for (int i = 0; i < 8; i++)
        #pragma unroll
        for (int j = 0; j < 4; j++) acc[i][j] = 0ULL;

    for (int kt = 0; kt < K; kt += BKt) {
        // ---- load A tile [BM x BK], transpose + duplicate into AsD ----
        #pragma unroll
        for (int rep = 0; rep < 2; rep++) {
            int row = arow0 + rep * 64;
            float4 v = *(const float4*)(A + (size_t)(bm + row) * K + kt + ac4 * 4);
            int kk = ac4 * 4;
            *(float2*)&AsD[kk + 0][2 * row] = make_float2(v.x, v.x);
            *(float2*)&AsD[kk + 1][2 * row] = make_float2(v.y, v.y);
            *(float2*)&AsD[kk + 2][2 * row] = make_float2(v.z, v.z);
            *(float2*)&AsD[kk + 3][2 * row] = make_float2(v.w, v.w);
        }
        // ---- load B tile ----
        if (BT) {
            #pragma unroll
            for (int rep = 0; rep < 2; rep++) {
                int n = arow0 + rep * 64;
                float4 v = *(const float4*)(Bp + (size_t)(bn + n) * K + kt + ac4 * 4);
                int kk = ac4 * 4;
                Bs[kk + 0][n] = v.x;
                Bs[kk + 1][n] = v.y;
                Bs[kk + 2][n] = v.z;
                Bs[kk + 3][n] = v.w;
            }
        } else {
            #pragma unroll
            for (int rep = 0; rep < 2; rep++) {
                int r = br + rep * 8;
                float4 v = *(const float4*)(Bp + (size_t)(kt + r) * N + bn + bc4 * 4);
                *(float4*)&Bs[r][bc4 * 4] = v;
            }
        }
        __syncthreads();

        #pragma unroll
        for (int k = 0; k < BKt; k++) {
            unsigned long long ap[8], bp[4];
            const ulonglong2* a2 = (const ulonglong2*)&AsD[k][ty * 16];
            ulonglong2 t0 = a2[0], t1 = a2[1], t2 = a2[2], t3 = a2[3];
            ap[0] = t0.x; ap[1] = t0.y; ap[2] = t1.x; ap[3] = t1.y;
            ap[4] = t2.x; ap[5] = t2.y; ap[6] = t3.x; ap[7] = t3.y;
            const ulonglong2* b2 = (const ulonglong2*)&Bs[k][tx * 8];
            ulonglong2 u0 = b2[0], u1 = b2[1];
            bp[0] = u0.x; bp[1] = u0.y; bp[2] = u1.x; bp[3] = u1.y;
            #pragma unroll
            for (int i = 0; i < 8; i++)
                #pragma unroll
                for (int j = 0; j < 4; j++)
                    fma2(acc[i][j], ap[i], bp[j]);
        }
        __syncthreads();
    }

    // ---- epilogue ----
    float bv[8];
    if (HASBIAS) {
        float4 q0 = *(const float4*)(bias + bn + tx * 8);
        float4 q1 = *(const float4*)(bias + bn + tx * 8 + 4);
        bv[0]=q0.x; bv[1]=q0.y; bv[2]=q0.z; bv[3]=q0.w;
        bv[4]=q1.x; bv[5]=q1.y; bv[6]=q1.z; bv[7]=q1.w;
    } else {
        #pragma unroll
        for (int j = 0; j < 8; j++) bv[j] = 0.0f;
    }

    #pragma unroll
    for (int i = 0; i < 8; i++) {
        float* crow = C + (size_t)(bm + ty * 8 + i) * N + bn + tx * 8;
        float2 r0 = unpack2(acc[i][0]);
        float2 r1 = unpack2(acc[i][1]);
        float2 r2 = unpack2(acc[i][2]);
        float2 r3 = unpack2(acc[i][3]);
        float4 o0 = make_float4(r0.x * scale + bv[0], r0.y * scale + bv[1],
                                r1.x * scale + bv[2], r1.y * scale + bv[3]);
        float4 o1 = make_float4(r2.x * scale + bv[4], r2.y * scale + bv[5],
                                r3.x * scale + bv[6], r3.y * scale + bv[7]);
        *(float4*)crow       = o0;
        *(float4*)(crow + 4) = o1;
    }
}

// ---------------- ctx projections + gate scalars ----------------
// grid (B, 2): y=0 -> (Wcq, g_qc, g_ctxq, g_cq), y=1 -> k variant
__global__ void ctx_prep_k(const float* __restrict__ ctx,
                           const float* __restrict__ Wcq, const float* __restrict__ Wck,
                           const float* __restrict__ gqc, const float* __restrict__ gkc)
{
    const int b = blockIdx.x, which = blockIdx.y, tid = threadIdx.x;
    __shared__ float cs[Hq];
    __shared__ float red[8];
    const float* W  = which ? Wck : Wcq;
    const float* gv = which ? gkc : gqc;
    float* dst = which ? g_ctxk : g_ctxq;

    #pragma unroll
    for (int i = 0; i < Hq / 256; i++)
        cs[tid + i * 256] = ctx[b * Hq + tid + i * 256];
    __syncthreads();

    // scalar: ctx . g
    float4 c4 = *(const float4*)&cs[tid * 4];
    float4 g4 = *(const float4*)&gv[tid * 4];
    float p = c4.x * g4.x + c4.y * g4.y + c4.z * g4.z + c4.w * g4.w;
    #pragma unroll
    for (int o = 16; o > 0; o >>= 1) p += __shfl_xor_sync(0xffffffffu, p, o);
    if ((tid & 31) == 0) red[tid >> 5] = p;
    __syncthreads();
    if (tid == 0) {
        float t = 0.f;
        #pragma unroll
        for (int i = 0; i < 8; i++) t += red[i];
        (which ? g_ck : g_cq)[b] = t;
    }

    // projection row: ctx @ W^T
    for (int o = tid; o < Hq; o += 256) {
        const float4* wr = (const float4*)(W + (size_t)o * Hq);
        float d = 0.f;
        #pragma unroll 4
        for (int h = 0; h < Hq / 4; h++) {
            float4 w = wr[h];
            float4 c = *(const float4*)&cs[h * 4];
            d += w.x * c.x + w.y * c.y + w.z * c.z + w.w * c.w;
        }
        dst[b * Hq + o] = d;
    }
}

// ---------------- gate + blend (in-place on Q/K buffers) ----------------
// grid (M, 2): y=0 -> Q, y=1 -> K. 256 threads, 1 row each.
__global__ void gate_blend_k(const float* __restrict__ gqh, const float* __restrict__ gkh)
{
    const int m = blockIdx.x, which = blockIdx.y, tid = threadIdx.x;
    const int b = m >> 11;   // m / 2048
    float* P = (which ? g_Kb : g_Qb) + (size_t)m * Hq;
    const float* gv   = which ? gkh : gqh;
    const float* cvec = (which ? g_ctxk : g_ctxq) + b * Hq;
    const float  csc  = (which ? g_ck : g_cq)[b];

    __shared__ float red[8];
    __shared__ float gsh;

    float4 p4 = *(const float4*)&P[tid * 4];
    float4 g4 = *(const float4*)&gv[tid * 4];
    float p = p4.x * g4.x + p4.y * g4.y + p4.z * g4.z + p4.w * g4.w;
    #pragma unroll
    for (int o = 16; o > 0; o >>= 1) p += __shfl_xor_sync(0xffffffffu, p, o);
    if ((tid & 31) == 0) red[tid >> 5] = p;
    __syncthreads();
    if (tid == 0) {
        float t = 0.f;
        #pragma unroll
        for (int i = 0; i < 8; i++) t += red[i];
        gsh = 1.0f / (1.0f + expf(-(t + csc)));
    }
    __syncthreads();
    const float g = gsh;
    float4 c4 = *(const float4*)&cvec[tid * 4];
    float4 o;
    o.x = (1.0f - g) * p4.x + g * c4.x;
    o.y = (1.0f - g) * p4.y + g * c4.y;
    o.z = (1.0f - g) * p4.z + g * c4.z;
    o.w = (1.0f - g) * p4.w + g * c4.w;
    *(float4*)&P[tid * 4] = o;
}

// ---------------- softmax over rows of length S ----------------
__global__ void softmax_k(const float* __restrict__ in, float* __restrict__ out)
{
    const int r = blockIdx.x, tid = threadIdx.x;
    const float* p = in  + (size_t)r * Sq;
    float*       q = out + (size_t)r * Sq;
    __shared__ float red[8];
    __shared__ float bc;

    float4 x0 = *(const float4*)&p[tid * 8];
    float4 x1 = *(const float4*)&p[tid * 8 + 4];

    float m = fmaxf(fmaxf(fmaxf(x0.x, x0.y), fmaxf(x0.z, x0.w)),
                    fmaxf(fmaxf(x1.x, x1.y), fmaxf(x1.z, x1.w)));
    #pragma unroll
    for (int o = 16; o > 0; o >>= 1) m = fmaxf(m, __shfl_xor_sync(0xffffffffu, m, o));
    if ((tid & 31) == 0) red[tid >> 5] = m;
    __syncthreads();
    if (tid == 0) {
        float t = red[0];
        #pragma unroll
        for (int i = 1; i < 8; i++) t = fmaxf(t, red[i]);
        bc = t;
    }
    __syncthreads();
    const float mx = bc;
    __syncthreads();   // protect red before reuse

    float4 e0, e1;
    e0.x = expf(x0.x - mx); e0.y = expf(x0.y - mx);
    e0.z = expf(x0.z - mx); e0.w = expf(x0.w - mx);
    e1.x = expf(x1.x - mx); e1.y = expf(x1.y - mx);
    e1.z = expf(x1.z - mx); e1.w = expf(x1.w - mx);

    float s = e0.x + e0.y + e0.z + e0.w + e1.x + e1.y + e1.z + e1.w;
    #pragma unroll
    for (int o = 16; o > 0; o >>= 1) s += __shfl_xor_sync(0xffffffffu, s, o);
    if ((tid & 31) == 0) red[tid >> 5] = s;
    __syncthreads();
    if (tid == 0) {
        float t = 0.f;
        #pragma unroll
        for (int i = 0; i < 8; i++) t += red[i];
        bc = 1.0f / t;
    }
    __syncthreads();
    const float inv = bc;

    e0.x *= inv; e0.y *= inv; e0.z *= inv; e0.w *= inv;
    e1.x *= inv; e1.y *= inv; e1.z *= inv; e1.w *= inv;
    *(float4*)&q[tid * 8]     = e0;
    *(float4*)&q[tid * 8 + 4] = e1;
}

// ---------------- launch ----------------
extern "C" void kernel_launch(void* const* d_in, const int* in_sizes, int n_in,
                              void* d_out, int out_size)
{
    const float* X   = (const float*)d_in[0];
    const float* ctx = (const float*)d_in[1];
    const float* Wq  = (const float*)d_in[2];
    const float* bq  = (const float*)d_in[3];
    const float* Wk  = (const float*)d_in[4];
    const float* bk  = (const float*)d_in[5];
    const float* Wv  = (const float*)d_in[6];
    const float* bv  = (const float*)d_in[7];
    const float* Wcq = (const float*)d_in[8];
    const float* Wck = (const float*)d_in[9];
    const float* gqh = (const float*)d_in[10];
    const float* gkh = (const float*)d_in[11];
    const float* gqc = (const float*)d_in[12];
    const float* gkc = (const float*)d_in[13];

    float* out    = (float*)d_out;                  // [B,S,H]
    float* scores = out + (size_t)Mq * Hq;          // [B,S,S]

    float *Qb, *Kb, *Vb, *Pb;
    cudaGetSymbolAddress((void**)&Qb, g_Qb);
    cudaGetSymbolAddress((void**)&Kb, g_Kb);
    cudaGetSymbolAddress((void**)&Vb, g_Vb);
    cudaGetSymbolAddress((void**)&Pb, g_Pb);

    dim3 blk(256);

    // 1) QKV projections: [M,H] = X[M,H] @ W^T[H,H] + b
    dim3 gq(Hq / BNt, Mq / BMt, 1);
    sgemm_k<true,  true ><<<gq, blk>>>(X, Wq, Qb, bq, Mq, Hq, Hq, 0, 0, 0, 1.0f);
    sgemm_k<true,  true ><<<gq, blk>>>(X, Wk, Kb, bk, Mq, Hq, Hq, 0, 0, 0, 1.0f);
    sgemm_k<true,  true ><<<gq, blk>>>(X, Wv, Vb, bv, Mq, Hq, Hq, 0, 0, 0, 1.0f);

    // 2) ctx projections + gate scalars
    ctx_prep_k<<<dim3(Bq, 2), blk>>>(ctx, Wcq, Wck, gqc, gkc);

    // 3) gate + blend in place on Q/K
    gate_blend_k<<<dim3(Mq, 2), blk>>>(gqh, gkh);

    // 4) scores = q_hat @ k_hat^T / sqrt(H), written straight to output region
    sgemm_k<true,  false><<<dim3(Sq / BNt, Sq / BMt, Bq), blk>>>(
        Qb, Kb, scores, nullptr, Sq, Sq, Hq,
        (long long)Sq * Hq, (long long)Sq * Hq, (long long)Sq * Sq, 0.03125f);

    // 5) softmax rows
    softmax_k<<<dim3(Bq * Sq), blk>>>(scores, Pb);

    // 6) output = probs @ V
    sgemm_k<false, false><<<dim3(Hq / BNt, Sq / BMt, Bq), blk>>>(
        Pb, Vb, out, nullptr, Sq, Hq, Sq,
        (long long)Sq * Sq, (long long)Sq * Hq, (long long)Sq * Hq, 1.0f);
}

// round 3
// speedup vs baseline: 3.1328x; 3.1328x over previous
#include <cuda_runtime.h>
#include <cstdint>

// Problem constants
#define Bq 8
#define Sq 2048
#define Hq 1024
#define Mq (Bq*Sq)   // 16384

// ---------------- scratch (device globals; no cudaMalloc allowed) ----------
__device__ float g_Qb[(size_t)Mq*Hq];          // 64 MB  q_hat
__device__ float g_Kb[(size_t)Mq*Hq];          // 64 MB  k_hat
__device__ float g_Vt[(size_t)Bq*Hq*Sq];       // 64 MB  V transposed [B][H][S]
__device__ float g_Pb[(size_t)Bq*Sq*Sq];       // 134 MB softmax probs
__device__ float g_ctxq[Bq*Hq];
__device__ float g_ctxk[Bq*Hq];
__device__ float g_cq[Bq];
__device__ float g_ck[Bq];

// ---------------- helpers ----------------
static __device__ __forceinline__ uint32_t f2tf(float f) {
    uint32_t r; asm("cvt.rna.tf32.f32 %0, %1;" : "=r"(r) : "f"(f)); return r;
}
static __device__ __forceinline__ void mma_tf32(float& c0, float& c1, float& c2, float& c3,
                                                uint32_t a0, uint32_t a1, uint32_t a2, uint32_t a3,
                                                uint32_t b0, uint32_t b1) {
    asm("mma.sync.aligned.m16n8k8.row.col.f32.tf32.tf32.f32 "
        "{%0,%1,%2,%3}, {%4,%5,%6,%7}, {%8,%9}, {%0,%1,%2,%3};"
        : "+f"(c0), "+f"(c1), "+f"(c2), "+f"(c3)
        : "r"(a0), "r"(a1), "r"(a2), "r"(a3), "r"(b0), "r"(b1));
}

// =================== tf32 mma.sync GEMM ===================
// C[M,N] = A[M,K] @ B[N,K]^T * scale (+bias[n]).  Row-major, both K-major (NT).
// TRANSOUT: write to Cg[((m>>11)*Hq + n)*Sq + (m&2047)]  (V transpose path)
#define BMg 128
#define BNg 128
#define BKg 16
#define RSTRIDE 20   // floats per SMEM row (16 data + 4 pad) -> conflict-free frags

template<bool HASBIAS, bool TRANSOUT>
__global__ void __launch_bounds__(256, 2)
mma_gemm(const float* __restrict__ Ag, const float* __restrict__ Bg,
         float* __restrict__ Cg, const float* __restrict__ bias,
         int M, int N, int K,
         long long sA_, long long sB_, long long sC_, float scale)
{
    __shared__ uint32_t sA[2][BMg * RSTRIDE];   // tf32 bits
    __shared__ uint32_t sB[2][BNg * RSTRIDE];

    const float* A  = Ag + (long long)blockIdx.z * sA_;
    const float* Bp = Bg + (long long)blockIdx.z * sB_;
    float*       C  = Cg + (long long)blockIdx.z * sC_;
    const int bm = blockIdx.y * BMg;
    const int bn = blockIdx.x * BNg;

    const int tid  = threadIdx.x;
    const int wid  = tid >> 5, lane = tid & 31;
    const int g    = lane >> 2, t4 = lane & 3;
    const int wm   = (wid & 3) * 32;      // 4 warps in M
    const int wn   = (wid >> 2) * 64;     // 2 warps in N

    // loader mapping: per thread 2 rows each for A and B
    const int arow = tid >> 2;            // 0..63
    const int ac4  = tid & 3;             // float4 column
    const float* pA0 = A  + (size_t)(bm + arow)      * K + ac4 * 4;
    const float* pA1 = A  + (size_t)(bm + arow + 64) * K + ac4 * 4;
    const float* pB0 = Bp + (size_t)(bn + arow)      * K + ac4 * 4;
    const float* pB1 = Bp + (size_t)(bn + arow + 64) * K + ac4 * 4;

    float acc[2][8][4];
    #pragma unroll
    for (int mt = 0; mt < 2; mt++)
        #pragma unroll
        for (int nt = 0; nt < 8; nt++)
            #pragma unroll
            for (int j = 0; j < 4; j++) acc[mt][nt][j] = 0.0f;

    const int NC = K / BKg;

    // ---- prologue: chunk 0 ----
    {
        float4 a0 = *(const float4*)pA0;
        float4 a1 = *(const float4*)pA1;
        float4 b0 = *(const float4*)pB0;
        float4 b1 = *(const float4*)pB1;
        *(uint4*)&sA[0][arow * RSTRIDE + ac4 * 4] =
            make_uint4(f2tf(a0.x), f2tf(a0.y), f2tf(a0.z), f2tf(a0.w));
        *(uint4*)&sA[0][(arow + 64) * RSTRIDE + ac4 * 4] =
            make_uint4(f2tf(a1.x), f2tf(a1.y), f2tf(a1.z), f2tf(a1.w));
        *(uint4*)&sB[0][arow * RSTRIDE + ac4 * 4] =
            make_uint4(f2tf(b0.x), f2tf(b0.y), f2tf(b0.z), f2tf(b0.w));
        *(uint4*)&sB[0][(arow + 64) * RSTRIDE + ac4 * 4] =
            make_uint4(f2tf(b1.x), f2tf(b1.y), f2tf(b1.z), f2tf(b1.w));
    }
    __syncthreads();

    for (int kt = 0; kt < NC; kt++) {
        const int s = kt & 1;
        float4 a0r, a1r, b0r, b1r;
        if (kt + 1 < NC) {
            const int kof = (kt + 1) * BKg;
            a0r = *(const float4*)(pA0 + kof);
            a1r = *(const float4*)(pA1 + kof);
            b0r = *(const float4*)(pB0 + kof);
            b1r = *(const float4*)(pB1 + kof);
        }

        // ---- MMA on stage s ----
        #pragma unroll
        for (int ks = 0; ks < 2; ks++) {
            uint32_t af[2][4];
            #pragma unroll
            for (int mt = 0; mt < 2; mt++) {
                const uint32_t* p = &sA[s][(wm + mt * 16 + g) * RSTRIDE + ks * 8 + t4];
                af[mt][0] = p[0];
                af[mt][1] = p[8 * RSTRIDE];
                af[mt][2] = p[4];
                af[mt][3] = p[8 * RSTRIDE + 4];
            }
            #pragma unroll
            for (int nt = 0; nt < 8; nt++) {
                const uint32_t* p = &sB[s][(wn + nt * 8 + g) * RSTRIDE + ks * 8 + t4];
                uint32_t b0 = p[0], b1 = p[4];
                mma_tf32(acc[0][nt][0], acc[0][nt][1], acc[0][nt][2], acc[0][nt][3],
                         af[0][0], af[0][1], af[0][2], af[0][3], b0, b1);
                mma_tf32(acc[1][nt][0], acc[1][nt][1], acc[1][nt][2], acc[1][nt][3],
                         af[1][0], af[1][1], af[1][2], af[1][3], b0, b1);
            }
        }

        if (kt + 1 < NC) {
            const int t = s ^ 1;
            *(uint4*)&sA[t][arow * RSTRIDE + ac4 * 4] =
                make_uint4(f2tf(a0r.x), f2tf(a0r.y), f2tf(a0r.z), f2tf(a0r.w));
            *(uint4*)&sA[t][(arow + 64) * RSTRIDE + ac4 * 4] =
                make_uint4(f2tf(a1r.x), f2tf(a1r.y), f2tf(a1r.z), f2tf(a1r.w));
            *(uint4*)&sB[t][arow * RSTRIDE + ac4 * 4] =
                make_uint4(f2tf(b0r.x), f2tf(b0r.y), f2tf(b0r.z), f2tf(b0r.w));
            *(uint4*)&sB[t][(arow + 64) * RSTRIDE + ac4 * 4] =
                make_uint4(f2tf(b1r.x), f2tf(b1r.y), f2tf(b1r.z), f2tf(b1r.w));
            __syncthreads();
        }
    }

    // ---- epilogue ----
    #pragma unroll
    for (int mt = 0; mt < 2; mt++) {
        #pragma unroll
        for (int half = 0; half < 2; half++) {
            const int r = bm + wm + mt * 16 + g + half * 8;   // global m
            if (!TRANSOUT) {
                float* crow = C + (size_t)r * N + bn + wn;
                #pragma unroll
                for (int nt = 0; nt < 8; nt++) {
                    const int co = nt * 8 + 2 * t4;
                    float v0 = acc[mt][nt][half * 2 + 0] * scale;
                    float v1 = acc[mt][nt][half * 2 + 1] * scale;
                    if (HASBIAS) {
                        float2 bb = *(const float2*)&bias[bn + wn + co];
                        v0 += bb.x; v1 += bb.y;
                    }
                    *(float2*)&crow[co] = make_float2(v0, v1);
                }
            } else {
                const int b = r >> 11, srow = r & 2047;
                #pragma unroll
                for (int nt = 0; nt < 8; nt++) {
                    const int n = bn + wn + nt * 8 + 2 * t4;
                    float v0 = acc[mt][nt][half * 2 + 0] * scale;
                    float v1 = acc[mt][nt][half * 2 + 1] * scale;
                    if (HASBIAS) {
                        float2 bb = *(const float2*)&bias[n];
                        v0 += bb.x; v1 += bb.y;
                    }
                    Cg[((size_t)b * Hq + n)     * Sq + srow] = v0;
                    Cg[((size_t)b * Hq + n + 1) * Sq + srow] = v1;
                }
            }
        }
    }
}

// ---------------- ctx projections + gate scalars ----------------
// grid (B, 2, 8): each block computes 128 outputs; z==0 also computes the gate scalar.
__global__ void __launch_bounds__(128) ctx_prep_k(
    const float* __restrict__ ctx,
    const float* __restrict__ Wcq, const float* __restrict__ Wck,
    const float* __restrict__ gqc, const float* __restrict__ gkc)
{
    const int b = blockIdx.x, which = blockIdx.y, z = blockIdx.z, tid = threadIdx.x;
    __shared__ float cs[Hq];
    __shared__ float red[4];
    const float* W  = which ? Wck : Wcq;
    const float* gv = which ? gkc : gqc;
    float* dst = which ? g_ctxk : g_ctxq;

    for (int i = tid; i < Hq; i += 128) cs[i] = ctx[b * Hq + i];
    __syncthreads();

    if (z == 0) {
        float p = 0.f;
        for (int i = tid; i < Hq; i += 128) p += cs[i] * gv[i];
        #pragma unroll
        for (int o = 16; o > 0; o >>= 1) p += __shfl_xor_sync(0xffffffffu, p, o);
        if ((tid & 31) == 0) red[tid >> 5] = p;
        __syncthreads();
        if (tid == 0)
            (which ? g_ck : g_cq)[b] = red[0] + red[1] + red[2] + red[3];
    }

    const int o = z * 128 + tid;
    const float4* wr = (const float4*)(W + (size_t)o * Hq);
    float d = 0.f;
    #pragma unroll 4
    for (int h = 0; h < Hq / 4; h++) {
        float4 w = wr[h];
        float4 c = *(const float4*)&cs[h * 4];
        d += w.x * c.x + w.y * c.y + w.z * c.z + w.w * c.w;
    }
    dst[b * Hq + o] = d;
}

// ---------------- gate + blend (in-place on Q/K buffers) ----------------
__global__ void gate_blend_k(const float* __restrict__ gqh, const float* __restrict__ gkh)
{
    const int m = blockIdx.x, which = blockIdx.y, tid = threadIdx.x;
    const int b = m >> 11;
    float* P = (which ? g_Kb : g_Qb) + (size_t)m * Hq;
    const float* gv   = which ? gkh : gqh;
    const float* cvec = (which ? g_ctxk : g_ctxq) + b * Hq;
    const float  csc  = (which ? g_ck : g_cq)[b];

    __shared__ float red[8];
    __shared__ float gsh;

    float4 p4 = *(const float4*)&P[tid * 4];
    float4 g4 = *(const float4*)&gv[tid * 4];
    float p = p4.x * g4.x + p4.y * g4.y + p4.z * g4.z + p4.w * g4.w;
    #pragma unroll
    for (int o = 16; o > 0; o >>= 1) p += __shfl_xor_sync(0xffffffffu, p, o);
    if ((tid & 31) == 0) red[tid >> 5] = p;
    __syncthreads();
    if (tid == 0) {
        float t = 0.f;
        #pragma unroll
        for (int i = 0; i < 8; i++) t += red[i];
        gsh = 1.0f / (1.0f + expf(-(t + csc)));
    }
    __syncthreads();
    const float g = gsh;
    float4 c4 = *(const float4*)&cvec[tid * 4];
    float4 o;
    o.x = (1.0f - g) * p4.x + g * c4.x;
    o.y = (1.0f - g) * p4.y + g * c4.y;
    o.z = (1.0f - g) * p4.z + g * c4.z;
    o.w = (1.0f - g) * p4.w + g * c4.w;
    *(float4*)&P[tid * 4] = o;
}

// ---------------- softmax over rows of length S ----------------
__global__ void softmax_k(const float* __restrict__ in, float* __restrict__ out)
{
    const int r = blockIdx.x, tid = threadIdx.x;
    const float* p = in  + (size_t)r * Sq;
    float*       q = out + (size_t)r * Sq;
    __shared__ float red[8];
    __shared__ float bc;

    float4 x0 = *(const float4*)&p[tid * 8];
    float4 x1 = *(const float4*)&p[tid * 8 + 4];

    float m = fmaxf(fmaxf(fmaxf(x0.x, x0.y), fmaxf(x0.z, x0.w)),
                    fmaxf(fmaxf(x1.x, x1.y), fmaxf(x1.z, x1.w)));
    #pragma unroll
    for (int o = 16; o > 0; o >>= 1) m = fmaxf(m, __shfl_xor_sync(0xffffffffu, m, o));
    if ((tid & 31) == 0) red[tid >> 5] = m;
    __syncthreads();
    if (tid == 0) {
        float t = red[0];
        #pragma unroll
        for (int i = 1; i < 8; i++) t = fmaxf(t, red[i]);
        bc = t;
    }
    __syncthreads();
    const float mx = bc;
    __syncthreads();

    float4 e0, e1;
    e0.x = expf(x0.x - mx); e0.y = expf(x0.y - mx);
    e0.z = expf(x0.z - mx); e0.w = expf(x0.w - mx);
    e1.x = expf(x1.x - mx); e1.y = expf(x1.y - mx);
    e1.z = expf(x1.z - mx); e1.w = expf(x1.w - mx);

    float s = e0.x + e0.y + e0.z + e0.w + e1.x + e1.y + e1.z + e1.w;
    #pragma unroll
    for (int o = 16; o > 0; o >>= 1) s += __shfl_xor_sync(0xffffffffu, s, o);
    if ((tid & 31) == 0) red[tid >> 5] = s;
    __syncthreads();
    if (tid == 0) {
        float t = 0.f;
        #pragma unroll
        for (int i = 0; i < 8; i++) t += red[i];
        bc = 1.0f / t;
    }
    __syncthreads();
    const float inv = bc;

    e0.x *= inv; e0.y *= inv; e0.z *= inv; e0.w *= inv;
    e1.x *= inv; e1.y *= inv; e1.z *= inv; e1.w *= inv;
    *(float4*)&q[tid * 8]     = e0;
    *(float4*)&q[tid * 8 + 4] = e1;
}

// ---------------- launch ----------------
extern "C" void kernel_launch(void* const* d_in, const int* in_sizes, int n_in,
                              void* d_out, int out_size)
{
    const float* X   = (const float*)d_in[0];
    const float* ctx = (const float*)d_in[1];
    const float* Wq  = (const float*)d_in[2];
    const float* bq  = (const float*)d_in[3];
    const float* Wk  = (const float*)d_in[4];
    const float* bk  = (const float*)d_in[5];
    const float* Wv  = (const float*)d_in[6];
    const float* bv  = (const float*)d_in[7];
    const float* Wcq = (const float*)d_in[8];
    const float* Wck = (const float*)d_in[9];
    const float* gqh = (const float*)d_in[10];
    const float* gkh = (const float*)d_in[11];
    const float* gqc = (const float*)d_in[12];
    const float* gkc = (const float*)d_in[13];

    float* out    = (float*)d_out;                  // [B,S,H]
    float* scores = out + (size_t)Mq * Hq;          // [B,S,S]

    float *Qb, *Kb, *Vt, *Pb;
    cudaGetSymbolAddress((void**)&Qb, g_Qb);
    cudaGetSymbolAddress((void**)&Kb, g_Kb);
    cudaGetSymbolAddress((void**)&Vt, g_Vt);
    cudaGetSymbolAddress((void**)&Pb, g_Pb);

    dim3 blk(256);

    // 1) Q/K projections: [M,H] = X @ W^T + b   (NT)
    dim3 gq(Hq / BNg, Mq / BMg, 1);
    mma_gemm<true, false><<<gq, blk>>>(X, Wq, Qb, bq, Mq, Hq, Hq, 0, 0, 0, 1.0f);
    mma_gemm<true, false><<<gq, blk>>>(X, Wk, Kb, bk, Mq, Hq, Hq, 0, 0, 0, 1.0f);
    // 2) V projection, written transposed into Vt[B][H][S]
    mma_gemm<true, true ><<<gq, blk>>>(X, Wv, Vt, bv, Mq, Hq, Hq, 0, 0, 0, 1.0f);

    // 3) ctx projections + gate scalars
    ctx_prep_k<<<dim3(Bq, 2, 8), dim3(128)>>>(ctx, Wcq, Wck, gqc, gkc);

    // 4) gate + blend in place on Q/K
    gate_blend_k<<<dim3(Mq, 2), dim3(256)>>>(gqh, gkh);

    // 5) scores = q_hat @ k_hat^T / sqrt(H) -> straight into output region
    mma_gemm<false, false><<<dim3(Sq / BNg, Sq / BMg, Bq), blk>>>(
        Qb, Kb, scores, nullptr, Sq, Sq, Hq,
        (long long)Sq * Hq, (long long)Sq * Hq, (long long)Sq * Sq, 0.03125f);

    // 6) softmax rows
    softmax_k<<<dim3(Bq * Sq), dim3(256)>>>(scores, Pb);

    // 7) output = probs @ V  (= probs[M=S,K=S] @ Vt[N=H,K=S]^T, NT)
    mma_gemm<false, false><<<dim3(Hq / BNg, Sq / BMg, Bq), blk>>>(
        Pb, Vt, out, nullptr, Sq, Hq, Sq,
        (long long)Sq * Sq, (long long)Hq * Sq, (long long)Sq * Hq, 1.0f);
}